// round 16
// baseline (speedup 1.0000x reference)
#include <cuda_runtime.h>
#include <cuda_bf16.h>
#include <cstdint>
#include <math.h>

#define B_ 128
#define N_ 784
#define C_ 512
#define K_ 64
#define APAD 72      // padded row length (bf16): conflict-free ldmatrix

// ---------------- scratch (no allocations allowed) -------------------------
__device__ __align__(16) __nv_bfloat16 g_an_bf16[8][K_][APAD];   // per-chunk anchor tiles

__device__ __forceinline__ uint32_t smem_u32(const void* p) {
    uint32_t a;
    asm("{ .reg .u64 t; cvta.to.shared.u64 t, %1; cvt.u32.u64 %0, t; }" : "=r"(a) : "l"(p));
    return a;
}

#define LDSM4(r0, r1, r2, r3, addr) \
    asm volatile("ldmatrix.sync.aligned.m8n8.x4.shared.b16 {%0,%1,%2,%3}, [%4];" \
                 : "=r"(r0), "=r"(r1), "=r"(r2), "=r"(r3) : "r"(addr))

__device__ __forceinline__ void mma_bf16(float d[4], const uint32_t a[4],
                                         uint32_t b0, uint32_t b1) {
    asm volatile(
        "mma.sync.aligned.m16n8k16.row.col.f32.bf16.bf16.f32 "
        "{%0,%1,%2,%3}, {%4,%5,%6,%7}, {%8,%9}, {%0,%1,%2,%3};"
        : "+f"(d[0]), "+f"(d[1]), "+f"(d[2]), "+f"(d[3])
        : "r"(a[0]), "r"(a[1]), "r"(a[2]), "r"(a[3]), "r"(b0), "r"(b1));
}

__device__ __forceinline__ float sigmoidf_(float t) {
    if (t >= 0.f) { float e = __expf(-t); return 1.f / (1.f + e); }
    float e = __expf(t); return e / (1.f + e);
}

// ---------------------------------------------------------------------------
// Kernel 1: normalize anchors -> bf16 per-chunk padded tiles. grid=64, blk=128.
// ---------------------------------------------------------------------------
__global__ void __launch_bounds__(128) anchor_kernel(const float* __restrict__ kern) {
    int k = blockIdx.x;
    int tid = threadIdx.x;
    __shared__ float red[4];
    float s = 0.f;
    for (int c = tid; c < C_; c += 128) { float v = kern[k * C_ + c]; s += v * v; }
#pragma unroll
    for (int o = 16; o; o >>= 1) s += __shfl_xor_sync(0xffffffffu, s, o);
    if ((tid & 31) == 0) red[tid >> 5] = s;
    __syncthreads();
    float inv = 1.f / (sqrtf(red[0] + red[1] + red[2] + red[3]) + 1e-12f);
    for (int p = tid; p < 256; p += 128) {
        int c = p * 2;
        int kc = c >> 6, cc = c & 63;
        __nv_bfloat162 h = __floats2bfloat162_rn(kern[k * C_ + c] * inv,
                                                 kern[k * C_ + c + 1] * inv);
        *reinterpret_cast<__nv_bfloat162*>(&g_an_bf16[kc][k][cc]) = h;
    }
}

// ---------------------------------------------------------------------------
// Fused kernel: one block per batch (grid=128), 512 threads = 16 FULLY
// INDEPENDENT warps in phase 1 (no cross-warp barriers in the mainloop).
// Each warp: 16-row x 512 GEMM tile vs all 64 anchors; A staged into a
// warp-PRIVATE double buffer (2 x 2304 B), B from block-shared anchor tiles.
// 49 tiles of 16 rows: warp w owns tiles {w, w+16, w+32} (+48 on warp 0).
// Row norms / exp-sum epilogue are warp-local (shfl). Then block vsolve and
// 4-way-split weighted-mean phase 2 (reverse order for L2 reuse).
//
// smem map (bytes):
//   SA_ALL @0       73728   anchors [8][64][72] bf16
//   WA     @73728   73728   per-warp A double buffers: [16][2][2304]
//                            (phase2: cbuf 6144 overlays)
//   SLS    @147456   3136   logS -> weights (in place)
//   RED    @150592     64
//   VSH    @150656      4
// ---------------------------------------------------------------------------
#define SA_ALL  0u
#define PH_WA   73728u
#define PH_SLS  147456u
#define PH_RED  150592u
#define PH_VSH  150656u
#define SMEM_TOTAL 150720

__global__ void __launch_bounds__(512) fused_kernel(const float* __restrict__ x,
                                                    float* __restrict__ out) {
    extern __shared__ __align__(16) char smem[];
    const uint32_t sb = smem_u32(smem);
    const int tid = threadIdx.x;
    const int lane = tid & 31, wid = tid >> 5;
    const int b = blockIdx.x;

    // per-lane load mapping: r = lane&15 (row in tile), h = lane>>4 (col half)
    const int r = lane & 15, h = lane >> 4;
    // ldmatrix lane address components
    const uint32_t a_row = (uint32_t)(lane & 15);
    const uint32_t a_colb = (uint32_t)((lane >> 4) << 3);
    const uint32_t b_rowo = (uint32_t)((lane & 7) + ((lane >> 4) << 3));
    const uint32_t b_colo = (uint32_t)(lane & 8);

    const uint32_t wbuf = PH_WA + (uint32_t)wid * 4608u;   // 2 x 2304 B

    const float* xg = x + (size_t)b * N_ * C_;
    float* sls = reinterpret_cast<float*>(smem + PH_SLS);

    // cooperative anchor load (4608 uint4 over 512 threads = 9 each)
    {
        const uint4* src = reinterpret_cast<const uint4*>(g_an_bf16);
#pragma unroll
        for (int i = 0; i < 9; i++)
            reinterpret_cast<uint4*>(smem)[tid + 512 * i] = src[tid + 512 * i];
    }
    __syncthreads();   // anchors visible to all warps

    const int ntiles = (wid == 0) ? 4 : 3;
    const int nci = ntiles * 8;

    float acc[8][4];
#pragma unroll
    for (int t = 0; t < 8; t++)
#pragma unroll
        for (int i = 0; i < 4; i++) acc[t][i] = 0.f;
    float nsq = 0.f;

    float4 rx[8];   // RAW prefetched floats (no consumer until stage)

    auto tile_of = [&](int ci) -> int {
        int ti = ci >> 3;
        return (ti < 3) ? (wid + ti * 16) : 48;
    };
    auto prefetch = [&](int ci) {
        const int row0 = tile_of(ci) * 16 + r;
        const int col0 = (ci & 7) * 64 + h * 32;
        const float* src = xg + (size_t)row0 * C_ + col0;
#pragma unroll
        for (int j = 0; j < 8; j++)
            rx[j] = *reinterpret_cast<const float4*>(src + j * 4);
    };
    auto stage = [&](uint32_t aoff) {
#pragma unroll
        for (int j = 0; j < 8; j++) {
            float4 v = rx[j];
            nsq += v.x * v.x + v.y * v.y + v.z * v.z + v.w * v.w;
            __nv_bfloat162 h0 = __floats2bfloat162_rn(v.x, v.y);
            __nv_bfloat162 h1 = __floats2bfloat162_rn(v.z, v.w);
            uint32_t u0 = *reinterpret_cast<uint32_t*>(&h0);
            uint32_t u1 = *reinterpret_cast<uint32_t*>(&h1);
            uint32_t off = aoff + (uint32_t)(r * (APAD * 2) + (h * 8 + j) * 8);
            asm volatile("st.shared.v2.b32 [%0], {%1,%2};"
                         :: "r"(sb + off), "r"(u0), "r"(u1) : "memory");
        }
    };

    prefetch(0);

#pragma unroll 1
    for (int ci = 0; ci < nci; ci++) {
        const uint32_t aoff = wbuf + ((ci & 1) ? 2304u : 0u);
        const int kc = ci & 7;
        stage(aoff);
        __syncwarp();
        if (ci < nci - 1) prefetch(ci + 1);   // LDGs overlap MMA below

#pragma unroll
        for (int ks = 0; ks < 4; ks++) {
            uint32_t a[4];
            LDSM4(a[0], a[1], a[2], a[3],
                  sb + aoff + a_row * (APAD * 2) + (ks * 16 + a_colb) * 2);
#pragma unroll
            for (int nt = 0; nt < 4; nt++) {
                uint32_t b0, b1, b2, b3;
                LDSM4(b0, b1, b2, b3,
                      sb + SA_ALL + (uint32_t)kc * 9216u
                         + (nt * 16 + b_rowo) * (APAD * 2) + (ks * 16 + b_colo) * 2);
                mma_bf16(acc[2 * nt], a, b0, b1);
                mma_bf16(acc[2 * nt + 1], a, b2, b3);
            }
        }

        if (kc == 7) {                 // tile epilogue — warp-local
            const int tile = tile_of(ci);
            // row norm: lane r holds half of row r; combine halves
            float rowsum = nsq + __shfl_xor_sync(0xffffffffu, nsq, 16);
            nsq = 0.f;
            const int g = lane >> 2;
            float n0 = __shfl_sync(0xffffffffu, rowsum, g);        // row g
            float n1 = __shfl_sync(0xffffffffu, rowsum, g + 8);    // row g+8
            const float i0 = 20.f / (sqrtf(n0) + 1e-12f);
            const float i1 = 20.f / (sqrtf(n1) + 1e-12f);
            float p0 = 0.f, p1 = 0.f;
#pragma unroll
            for (int t = 0; t < 8; t++) {
                p0 += __expf(fmaf(i0, acc[t][0], -20.f)) + __expf(fmaf(i0, acc[t][1], -20.f));
                p1 += __expf(fmaf(i1, acc[t][2], -20.f)) + __expf(fmaf(i1, acc[t][3], -20.f));
#pragma unroll
                for (int i2 = 0; i2 < 4; i2++) acc[t][i2] = 0.f;
            }
            p0 += __shfl_xor_sync(0xffffffffu, p0, 1);
            p0 += __shfl_xor_sync(0xffffffffu, p0, 2);
            p1 += __shfl_xor_sync(0xffffffffu, p1, 1);
            p1 += __shfl_xor_sync(0xffffffffu, p1, 2);
            if ((lane & 3) == 0) {
                sls[tile * 16 + g] = __logf(p0);
                sls[tile * 16 + 8 + g] = __logf(p1);
            }
        }
    }
    __syncthreads();    // all logS in smem

    // -------- in-block vsolve (10 iterations), 512 threads --------
    float* red = reinterpret_cast<float*>(smem + PH_RED);
    float* vshp = reinterpret_cast<float*>(smem + PH_VSH);
    float v = 0.f;
    const float logmu = logf(0.5f);
    const float logn = logf((float)N_);
    for (int it = 0; it < 10; ++it) {
        float part = 0.f;
        for (int n = tid; n < N_; n += 512) part += sigmoidf_(sls[n] + 10.f * v);
#pragma unroll
        for (int o = 16; o; o >>= 1) part += __shfl_xor_sync(0xffffffffu, part, o);
        if (lane == 0) red[wid] = part;
        __syncthreads();
        if (tid == 0) {
            float s = 0.f;
#pragma unroll
            for (int j = 0; j < 16; j++) s += red[j];
            vshp[0] = v + 0.1f * (logmu - (__logf(s) - logn));
        }
        __syncthreads();
        v = vshp[0];
    }
    for (int n = tid; n < N_; n += 512) sls[n] = 2.f * sigmoidf_(sls[n] + 10.f * v);
    __syncthreads();

    // -------- phase 2: weighted mean, 4-way n-split, reverse order ----------
    const int col4 = tid & 127;
    const int q = tid >> 7;                // quarter 0..3
    const int ntop = q * 196 + 195;        // descending from here
    const float4* xb4 = reinterpret_cast<const float4*>(xg);

    float4 a7[7];
#pragma unroll
    for (int j = 0; j < 7; j++) a7[j] = make_float4(0.f, 0.f, 0.f, 0.f);

#pragma unroll 1
    for (int i = 0; i < 196; i += 14) {    // 196 = 14*14
        float4 vv[14];
        float mm[14];
#pragma unroll
        for (int j = 0; j < 14; j++)
            vv[j] = xb4[(size_t)(ntop - (i + j)) * 128 + col4];
#pragma unroll
        for (int j = 0; j < 14; j++) mm[j] = sls[ntop - (i + j)];
#pragma unroll
        for (int j = 0; j < 7; j++) {
            a7[j].x += mm[j] * vv[j].x; a7[j].y += mm[j] * vv[j].y;
            a7[j].z += mm[j] * vv[j].z; a7[j].w += mm[j] * vv[j].w;
        }
#pragma unroll
        for (int j = 0; j < 7; j++) {
            a7[j].x += mm[j + 7] * vv[j + 7].x; a7[j].y += mm[j + 7] * vv[j + 7].y;
            a7[j].z += mm[j + 7] * vv[j + 7].z; a7[j].w += mm[j + 7] * vv[j + 7].w;
        }
    }
    float4 t;
    t.x = ((a7[0].x + a7[1].x) + (a7[2].x + a7[3].x)) + ((a7[4].x + a7[5].x) + a7[6].x);
    t.y = ((a7[0].y + a7[1].y) + (a7[2].y + a7[3].y)) + ((a7[4].y + a7[5].y) + a7[6].y);
    t.z = ((a7[0].z + a7[1].z) + (a7[2].z + a7[3].z)) + ((a7[4].z + a7[5].z) + a7[6].z);
    t.w = ((a7[0].w + a7[1].w) + (a7[2].w + a7[3].w)) + ((a7[4].w + a7[5].w) + a7[6].w);

    float4* cbuf = reinterpret_cast<float4*>(smem + PH_WA);   // 3x128 float4
    if (q > 0) cbuf[(q - 1) * 128 + col4] = t;
    __syncthreads();
    if (q == 0) {
        const float inv = 1.f / (float)N_;
        float4 o = t;
#pragma unroll
        for (int p = 0; p < 3; p++) {
            float4 c = cbuf[p * 128 + col4];
            o.x += c.x; o.y += c.y; o.z += c.z; o.w += c.w;
        }
        o.x *= inv; o.y *= inv; o.z *= inv; o.w *= inv;
        reinterpret_cast<float4*>(out + (size_t)b * C_)[col4] = o;
    }
}

// ---------------------------------------------------------------------------
extern "C" void kernel_launch(void* const* d_in, const int* in_sizes, int n_in,
                              void* d_out, int out_size) {
    const float* bow = (const float*)d_in[0];
    const float* kern = (const float*)d_in[1];
    if (n_in >= 2 && in_sizes[0] < in_sizes[1]) {  // defensive: pick by size
        const float* t = bow; bow = kern; kern = t;
    }
    static bool attr_set = false;
    if (!attr_set) {
        cudaFuncSetAttribute(fused_kernel, cudaFuncAttributeMaxDynamicSharedMemorySize,
                             SMEM_TOTAL);
        attr_set = true;
    }
    anchor_kernel<<<K_, 128>>>(kern);
    fused_kernel<<<B_, 512, SMEM_TOTAL>>>(bow, (float*)d_out);
}